// round 8
// baseline (speedup 1.0000x reference)
#include <cuda_runtime.h>
#include <cuda_fp16.h>
#include <math.h>
#include <stdint.h>

// ---------------------------------------------------------------------------
// Problem constants
// ---------------------------------------------------------------------------
#define BB   4
#define LL   4096
#define DD   1024
#define FFD  2048
#define MR   (BB*LL)          // 16384 rows
#define CCH  32               // conv chunks
#define CLEN 128              // conv chunk length

// ---------------------------------------------------------------------------
// Scratch (static __device__ arrays — allocation-free)
// ---------------------------------------------------------------------------
__device__ float  g_xn [(size_t)MR * DD];    // LN(x) fp32 (conv input)
__device__ float  g_c  [(size_t)MR * DD];    // conv output
__device__ float  g_x2 [(size_t)MR * DD];    // c*y + x
__device__ __half g_xh [(size_t)MR * DD];    // fp16 copy of x (GEMM0 A)
__device__ __half g_x3h[(size_t)MR * DD];    // fp16 LN(x2)    (GEMM1 A)
__device__ __half g_h1h[(size_t)MR * FFD];   // fp16 silu(x3@w1+b1) (GEMM2 A)
__device__ __half g_fcwT[(size_t)DD * DD];   // fc_w^T fp16 [N,K]
__device__ __half g_w1T [(size_t)FFD * DD];  // w1^T  fp16 [FF,D]
__device__ __half g_w2T [(size_t)DD * FFD];  // w2^T  fp16 [D,FF]
__device__ float  g_Ere[(size_t)BB * CCH * DD];
__device__ float  g_Eim[(size_t)BB * CCH * DD];

// ---------------------------------------------------------------------------
// PTX helpers (sm_100 base target — NO tcgen05)
// ---------------------------------------------------------------------------
__device__ __forceinline__ uint32_t smem_u32(const void* p) {
    uint32_t a;
    asm("{ .reg .u64 t; cvta.to.shared.u64 t, %1; cvt.u32.u64 %0, t; }"
        : "=r"(a) : "l"(p));
    return a;
}
__device__ __forceinline__ void cp16(uint32_t dst, const void* src) {
    asm volatile("cp.async.cg.shared.global [%0], [%1], 16;"
                 :: "r"(dst), "l"(src));
}
#define CP_COMMIT() asm volatile("cp.async.commit_group;" ::: "memory")
#define CP_WAIT1()  asm volatile("cp.async.wait_group 1;" ::: "memory")

__device__ __forceinline__ void ldsm4(uint32_t* r, uint32_t addr) {
    asm volatile("ldmatrix.sync.aligned.m8n8.x4.shared.b16 {%0,%1,%2,%3}, [%4];"
                 : "=r"(r[0]), "=r"(r[1]), "=r"(r[2]), "=r"(r[3]) : "r"(addr));
}
__device__ __forceinline__ void mma16816(float* c, const uint32_t* a,
                                         uint32_t b0, uint32_t b1) {
    asm volatile(
        "mma.sync.aligned.m16n8k16.row.col.f32.f16.f16.f32 "
        "{%0,%1,%2,%3},{%4,%5,%6,%7},{%8,%9},{%0,%1,%2,%3};"
        : "+f"(c[0]), "+f"(c[1]), "+f"(c[2]), "+f"(c[3])
        : "r"(a[0]), "r"(a[1]), "r"(a[2]), "r"(a[3]), "r"(b0), "r"(b1));
}

// ---------------------------------------------------------------------------
// LayerNorm kernels
// ---------------------------------------------------------------------------
__device__ __forceinline__ void ln_stats(const float4& v, int tid,
                                         float& mean, float& rstd) {
    float s = v.x + v.y + v.z + v.w;
    float q = v.x*v.x + v.y*v.y + v.z*v.z + v.w*v.w;
    #pragma unroll
    for (int o = 16; o > 0; o >>= 1) {
        s += __shfl_down_sync(0xffffffffu, s, o);
        q += __shfl_down_sync(0xffffffffu, q, o);
    }
    __shared__ float ss[8], qq[8];
    if ((tid & 31) == 0) { ss[tid >> 5] = s; qq[tid >> 5] = q; }
    __syncthreads();
    if (tid < 32) {
        float s2 = (tid < 8) ? ss[tid] : 0.f;
        float q2 = (tid < 8) ? qq[tid] : 0.f;
        #pragma unroll
        for (int o = 4; o > 0; o >>= 1) {
            s2 += __shfl_down_sync(0xffffffffu, s2, o);
            q2 += __shfl_down_sync(0xffffffffu, q2, o);
        }
        if (tid == 0) { ss[0] = s2; qq[0] = q2; }
    }
    __syncthreads();
    mean = ss[0] * (1.f / 1024.f);
    const float var = qq[0] * (1.f / 1024.f) - mean * mean;
    rstd = rsqrtf(var + 1e-5f);
}

// LN1: xn = LN(x) fp32, and xh = half(x raw)
__global__ void __launch_bounds__(256) ln1_kernel(
    const float* __restrict__ x, const float* __restrict__ g,
    const float* __restrict__ b, float* __restrict__ xn, __half* __restrict__ xh)
{
    const int row = blockIdx.x, tid = threadIdx.x;
    const float4 v = ((const float4*)x)[(size_t)row * 256 + tid];
    float mean, rstd;
    ln_stats(v, tid, mean, rstd);
    const float4 gg = ((const float4*)g)[tid];
    const float4 bb = ((const float4*)b)[tid];
    float4 o;
    o.x = (v.x - mean) * rstd * gg.x + bb.x;
    o.y = (v.y - mean) * rstd * gg.y + bb.y;
    o.z = (v.z - mean) * rstd * gg.z + bb.z;
    o.w = (v.w - mean) * rstd * gg.w + bb.w;
    ((float4*)xn)[(size_t)row * 256 + tid] = o;
    __half2 h01 = __floats2half2_rn(v.x, v.y);
    __half2 h23 = __floats2half2_rn(v.z, v.w);
    uint2 u; u.x = *(uint32_t*)&h01; u.y = *(uint32_t*)&h23;
    ((uint2*)xh)[(size_t)row * 256 + tid] = u;
}

// LN2: x3h = half(LN(x2))
__global__ void __launch_bounds__(256) ln2_kernel(
    const float* __restrict__ x2, const float* __restrict__ g,
    const float* __restrict__ b, __half* __restrict__ x3h)
{
    const int row = blockIdx.x, tid = threadIdx.x;
    const float4 v = ((const float4*)x2)[(size_t)row * 256 + tid];
    float mean, rstd;
    ln_stats(v, tid, mean, rstd);
    const float4 gg = ((const float4*)g)[tid];
    const float4 bb = ((const float4*)b)[tid];
    __half2 h01 = __floats2half2_rn((v.x - mean) * rstd * gg.x + bb.x,
                                    (v.y - mean) * rstd * gg.y + bb.y);
    __half2 h23 = __floats2half2_rn((v.z - mean) * rstd * gg.z + bb.z,
                                    (v.w - mean) * rstd * gg.w + bb.w);
    uint2 u; u.x = *(uint32_t*)&h01; u.y = *(uint32_t*)&h23;
    ((uint2*)x3h)[(size_t)row * 256 + tid] = u;
}

// ---------------------------------------------------------------------------
// Weight transpose + fp32 -> fp16:  src [K,N] -> dst [N,K]
// ---------------------------------------------------------------------------
__global__ void transpose_cvt(const float* __restrict__ src,
                              __half* __restrict__ dst, int K, int N)
{
    __shared__ float t[32][33];
    const int n0 = blockIdx.x * 32, k0 = blockIdx.y * 32;
    const int tx = threadIdx.x, ty = threadIdx.y;
    #pragma unroll
    for (int i = 0; i < 4; i++)
        t[ty + i * 8][tx] = src[(size_t)(k0 + ty + i * 8) * N + n0 + tx];
    __syncthreads();
    #pragma unroll
    for (int i = 0; i < 4; i++)
        dst[(size_t)(n0 + ty + i * 8) * K + k0 + tx] =
            __float2half_rn(t[tx][ty + i * 8]);
}

// ---------------------------------------------------------------------------
// Spiral conv: chunked linear recurrence (2 passes)
// ---------------------------------------------------------------------------
__device__ __forceinline__ void conv_phz(const float* ph_re, const float* ph_im,
                                         int d, float& zr, float& zi) {
    const float pr = ph_re[d], pim = ph_im[d];
    const float a  = sqrtf(pr * pr + pim * pim);
    const float sc = expf(-a) / a;
    zr = pr * sc; zi = pim * sc;
}

__global__ void __launch_bounds__(256) conv_pass1(
    const float* __restrict__ xn,
    const float* __restrict__ ph_re, const float* __restrict__ ph_im,
    float* __restrict__ Ere, float* __restrict__ Eim)
{
    const int idx = blockIdx.x * 256 + threadIdx.x;
    const int d = idx & 1023;
    const int rest = idx >> 10;
    const int b = rest >> 5;
    const int ck = rest & 31;
    float zr, zi; conv_phz(ph_re, ph_im, d, zr, zi);

    const float* xp = xn + ((size_t)b * LL + (size_t)ck * CLEN) * DD + d;
    float sr = 0.f, si = 0.f;
    #pragma unroll 4
    for (int t = 0; t < CLEN; t++) {
        const float xv = xp[(size_t)t * DD];
        const float nsr = fmaf(zr, sr, fmaf(-zi, si, xv));
        const float nsi = fmaf(zr, si, zi * sr);
        sr = nsr; si = nsi;
    }
    Ere[idx] = sr; Eim[idx] = si;
}

__global__ void __launch_bounds__(256) conv_pass3(
    const float* __restrict__ xn,
    const float* __restrict__ ph_re, const float* __restrict__ ph_im,
    const float* __restrict__ phi_re, const float* __restrict__ phi_im,
    const float* __restrict__ lci_re, const float* __restrict__ lci_im,
    const float* __restrict__ Ere, const float* __restrict__ Eim,
    float* __restrict__ c)
{
    const int idx = blockIdx.x * 256 + threadIdx.x;
    const int d = idx & 1023;
    const int rest = idx >> 10;
    const int b = rest >> 5;
    const int ck = rest & 31;
    float zr, zi; conv_phz(ph_re, ph_im, d, zr, zi);
    const float fr = phi_re[d], fj = phi_im[d];
    const float lr = lci_re[d], lj = lci_im[d];

    // w = phz^128 via 7 squarings
    float wr = zr, wi = zi;
    #pragma unroll
    for (int i = 0; i < 7; i++) {
        const float nr = wr * wr - wi * wi, ni = 2.f * wr * wi;
        wr = nr; wi = ni;
    }
    // p = w^ck (uniform per block -> no divergence)
    float pr = 1.f, pi = 0.f;
    int e = ck;
    float br = wr, bi = wi;
    while (e) {
        if (e & 1) { const float nr = pr * br - pi * bi, ni = pr * bi + pi * br; pr = nr; pi = ni; }
        const float nr = br * br - bi * bi, ni = 2.f * br * bi;
        br = nr; bi = ni;
        e >>= 1;
    }
    // u = lci * phz * p  (= lci * phz^(ck*128+1))
    const float tr = lr * zr - lj * zi, ti = lr * zi + lj * zr;
    float ur = tr * pr - ti * pi, ui = tr * pi + ti * pr;

    // chunk-initial state: s = sum_{cc<ck} w^(ck-1-cc) * E[cc]
    float sr = 0.f, si = 0.f;
    for (int cc = 0; cc < ck; cc++) {
        const size_t eo = ((size_t)(b * CCH + cc) << 10) + d;
        const float er = Ere[eo], ei = Eim[eo];
        const float nsr = wr * sr - wi * si + er;
        const float nsi = wr * si + wi * sr + ei;
        sr = nsr; si = nsi;
    }

    const float* xp = xn + ((size_t)b * LL + (size_t)ck * CLEN) * DD + d;
    float*       cp = c  + ((size_t)b * LL + (size_t)ck * CLEN) * DD + d;

#define CSTEP(XV, OUT) {                                   \
        const float nsr = fmaf(zr, sr, fmaf(-zi, si, (XV)));\
        const float nsi = fmaf(zr, si, zi * sr);            \
        sr = nsr; si = nsi;                                 \
        (OUT) = fmaf(fr, sr, fmaf(-fj, si, ur));            \
        const float nur = zr * ur - zi * ui;                \
        const float nui = zr * ui + zi * ur;                \
        ur = nur; ui = nui; }

    for (int t = 0; t < CLEN; t += 4) {
        const float x0 = xp[0 * DD];
        const float x1 = xp[1 * DD];
        const float x2 = xp[2 * DD];
        const float x3 = xp[3 * DD];
        float c0, c1, c2, c3;
        CSTEP(x0, c0); CSTEP(x1, c1); CSTEP(x2, c2); CSTEP(x3, c3);
        cp[0 * DD] = c0; cp[1 * DD] = c1; cp[2 * DD] = c2; cp[3 * DD] = c3;
        xp += 4 * DD; cp += 4 * DD;
    }
#undef CSTEP
}

// ---------------------------------------------------------------------------
// fp16 mma.sync GEMM: out = epi(A[M,K] @ B^T + bias),  B stored [N,K] fp16.
//   BM=128, BN=256, BK=64, 3-stage cp.async pipeline, ldmatrix, m16n8k16.
//   8 warps in 2x4: wm = wid&1 (64 rows), wn = wid>>1 (64 cols).
//   WARP TILE 64x64: per k16 step 8 ldsm.x4 feed 32 MMAs -> 16 MAC/byte of
//   smem read (vs 10.7 at 64x32), moving the kernel from smem-BW-bound to
//   HMMA-bound. acc=128 regs => 1 CTA/SM (launch_bounds(256,1)).
//   MODE 0: out = silu(v)*P + Q   (fp32)
//   MODE 1: out = silu(v)         (fp16)
//   MODE 2: out = v + P           (fp32)
// SMEM row = 64 halves + 16B pad = 144B (stride 9 chunks mod 32 -> ldmatrix
// conflict-free). Stage = (128+256)*144 = 55296B; 3 stages = 165888B.
// ---------------------------------------------------------------------------
#define ROW_B    144                     // bytes per smem row (64 h + pad)
#define SLOT_A   (128 * ROW_B)           // 18432
#define SLOT_BYTES ((128 + 256) * ROW_B) // 55296
#define NSTAGE   3
#define GEMM_SMEM  (NSTAGE * SLOT_BYTES) // 165888

__device__ __forceinline__ void load_stage(uint32_t sslot,
                                           const __half* __restrict__ A,
                                           const __half* __restrict__ Bm,
                                           int bm, int bn, int K, int kt, int tid)
{
    const __half* ag = A + (size_t)bm * K + kt * 64;
    #pragma unroll
    for (int i = 0; i < 4; i++) {
        const int o = tid + 256 * i;           // 0..1023
        const int row = o >> 3, ch = o & 7;
        cp16(sslot + row * ROW_B + ch * 16, ag + (size_t)row * K + ch * 8);
    }
    const __half* bg = Bm + (size_t)bn * K + kt * 64;
    #pragma unroll
    for (int i = 0; i < 8; i++) {
        const int o = tid + 256 * i;           // 0..2047
        const int row = o >> 3, ch = o & 7;
        cp16(sslot + SLOT_A + row * ROW_B + ch * 16, bg + (size_t)row * K + ch * 8);
    }
}

template <int MODE>
__global__ void __launch_bounds__(256, 1)
gemm_hmma(const __half* __restrict__ A, const __half* __restrict__ Bm,
          const float* __restrict__ bias, const float* __restrict__ P,
          const float* __restrict__ Q, float* __restrict__ outF,
          __half* __restrict__ outH, int M, int N, int K)
{
    extern __shared__ char smem_raw[];
    const uint32_t sbase = smem_u32(smem_raw);

    const int tid = threadIdx.x, wid = tid >> 5, lane = tid & 31;
    const int wm = wid & 1, wn = wid >> 1;
    const int bm = blockIdx.y << 7, bn = blockIdx.x << 8;
    const int KT = K >> 6;

    // lane-dependent ldmatrix address part: row = lane&15, khalf = lane>>4
    const uint32_t lane_off = (uint32_t)(lane & 15) * ROW_B + (uint32_t)(lane >> 4) * 16;

    float acc[4][8][4];
    #pragma unroll
    for (int i = 0; i < 4; i++)
        #pragma unroll
        for (int j = 0; j < 8; j++)
            #pragma unroll
            for (int k = 0; k < 4; k++) acc[i][j][k] = 0.f;

    // prologue: stages 0..1
    #pragma unroll
    for (int s = 0; s < 2; s++) {
        load_stage(sbase + s * SLOT_BYTES, A, Bm, bm, bn, K, s, tid);
        CP_COMMIT();
    }

    int slot = 0, wslot = 2;
    for (int kt = 0; kt < KT; kt++) {
        CP_WAIT1();
        __syncthreads();

        const uint32_t sA = sbase + slot * SLOT_BYTES;
        const uint32_t sB = sA + SLOT_A;
        const uint32_t aw = sA + (uint32_t)(wm * 64) * ROW_B + lane_off;
        const uint32_t bw = sB + (uint32_t)(wn * 64) * ROW_B + lane_off;

        #pragma unroll
        for (int ks = 0; ks < 4; ks++) {
            uint32_t af[4][4], bf[4][4];
            #pragma unroll
            for (int mi = 0; mi < 4; mi++)
                ldsm4(af[mi], aw + (uint32_t)(mi * 16) * ROW_B + ks * 32);
            #pragma unroll
            for (int nj = 0; nj < 4; nj++)
                ldsm4(bf[nj], bw + (uint32_t)(nj * 16) * ROW_B + ks * 32);
            #pragma unroll
            for (int mi = 0; mi < 4; mi++)
                #pragma unroll
                for (int ni = 0; ni < 8; ni++) {
                    const int nj = ni >> 1, hi = ni & 1;
                    mma16816(acc[mi][ni], af[mi], bf[nj][hi], bf[nj][2 + hi]);
                }
        }

        const int kn = kt + 2;
        if (kn < KT)
            load_stage(sbase + wslot * SLOT_BYTES, A, Bm, bm, bn, K, kn, tid);
        CP_COMMIT();

        slot = (slot + 1 == NSTAGE) ? 0 : slot + 1;
        wslot = (wslot + 1 == NSTAGE) ? 0 : wslot + 1;
    }

    // ---------------- epilogue ----------------
    #pragma unroll
    for (int mi = 0; mi < 4; ++mi) {
        #pragma unroll
        for (int ni = 0; ni < 8; ++ni) {
            const int r0 = bm + wm * 64 + mi * 16 + (lane >> 2);
            const int c0 = bn + wn * 64 + ni * 8 + (lane & 3) * 2;
            const float2 bz = *(const float2*)(bias + c0);

            #pragma unroll
            for (int half = 0; half < 2; ++half) {
                const int r = r0 + half * 8;
                float v0 = acc[mi][ni][half * 2 + 0] + bz.x;
                float v1 = acc[mi][ni][half * 2 + 1] + bz.y;
                const size_t off = (size_t)r * N + c0;
                if (MODE == 0 || MODE == 1) {
                    v0 = v0 / (1.f + expf(-v0));
                    v1 = v1 / (1.f + expf(-v1));
                }
                if (MODE == 0) {
                    const float2 p = *(const float2*)(P + off);
                    const float2 q = *(const float2*)(Q + off);
                    v0 = fmaf(v0, p.x, q.x);
                    v1 = fmaf(v1, p.y, q.y);
                }
                if (MODE == 2) {
                    const float2 p = *(const float2*)(P + off);
                    v0 += p.x;
                    v1 += p.y;
                }
                if (MODE == 1) {
                    __half2 h = __floats2half2_rn(v0, v1);
                    *(uint32_t*)(outH + off) = *(uint32_t*)&h;
                } else {
                    *(float2*)(outF + off) = make_float2(v0, v1);
                }
            }
        }
    }
}

// ---------------------------------------------------------------------------
// kernel_launch
// Inputs: 0 x, 1 ln_g, 2 ln_b, 3 fc_w, 4 fc_b, 5 w1, 6 b1, 7 w2, 8 b2,
//         9 ph_re, 10 ph_im, 11 phi_re, 12 phi_im, 13 lci_re, 14 lci_im
// ---------------------------------------------------------------------------
extern "C" void kernel_launch(void* const* d_in, const int* in_sizes, int n_in,
                              void* d_out, int out_size)
{
    const float* x      = (const float*)d_in[0];
    const float* ln_g   = (const float*)d_in[1];
    const float* ln_b   = (const float*)d_in[2];
    const float* fc_w   = (const float*)d_in[3];
    const float* fc_b   = (const float*)d_in[4];
    const float* w1     = (const float*)d_in[5];
    const float* b1     = (const float*)d_in[6];
    const float* w2     = (const float*)d_in[7];
    const float* b2     = (const float*)d_in[8];
    const float* ph_re  = (const float*)d_in[9];
    const float* ph_im  = (const float*)d_in[10];
    const float* phi_re = (const float*)d_in[11];
    const float* phi_im = (const float*)d_in[12];
    const float* lci_re = (const float*)d_in[13];
    const float* lci_im = (const float*)d_in[14];
    float* out = (float*)d_out;

    void *p;
    cudaGetSymbolAddress(&p, g_xn);   float*  xn   = (float*)p;
    cudaGetSymbolAddress(&p, g_c);    float*  cc   = (float*)p;
    cudaGetSymbolAddress(&p, g_x2);   float*  x2   = (float*)p;
    cudaGetSymbolAddress(&p, g_xh);   __half* xh   = (__half*)p;
    cudaGetSymbolAddress(&p, g_x3h);  __half* x3h  = (__half*)p;
    cudaGetSymbolAddress(&p, g_h1h);  __half* h1h  = (__half*)p;
    cudaGetSymbolAddress(&p, g_fcwT); __half* fcwT = (__half*)p;
    cudaGetSymbolAddress(&p, g_w1T);  __half* w1T  = (__half*)p;
    cudaGetSymbolAddress(&p, g_w2T);  __half* w2T  = (__half*)p;
    cudaGetSymbolAddress(&p, g_Ere);  float*  Ere  = (float*)p;
    cudaGetSymbolAddress(&p, g_Eim);  float*  Eim  = (float*)p;

    cudaFuncSetAttribute(gemm_hmma<0>, cudaFuncAttributeMaxDynamicSharedMemorySize, GEMM_SMEM);
    cudaFuncSetAttribute(gemm_hmma<1>, cudaFuncAttributeMaxDynamicSharedMemorySize, GEMM_SMEM);
    cudaFuncSetAttribute(gemm_hmma<2>, cudaFuncAttributeMaxDynamicSharedMemorySize, GEMM_SMEM);

    // weight transpose + fp16 convert
    transpose_cvt<<<dim3(DD / 32, DD / 32),  dim3(32, 8)>>>(fc_w, fcwT, DD, DD);
    transpose_cvt<<<dim3(FFD / 32, DD / 32), dim3(32, 8)>>>(w1,   w1T,  DD, FFD);
    transpose_cvt<<<dim3(DD / 32, FFD / 32), dim3(32, 8)>>>(w2,   w2T,  FFD, DD);

    // 1) xn = LN(x), xh = half(x)
    ln1_kernel<<<MR, 256>>>(x, ln_g, ln_b, xn, xh);

    // 2) c = spiral_conv(xn) — 2-pass chunked scan
    conv_pass1<<<(BB * CCH * DD) / 256, 256>>>(xn, ph_re, ph_im, Ere, Eim);
    conv_pass3<<<(BB * CCH * DD) / 256, 256>>>(xn, ph_re, ph_im, phi_re, phi_im,
                                               lci_re, lci_im, Ere, Eim, cc);

    // 3) x2 = silu(x@fc_w + fc_b) * c + x
    gemm_hmma<0><<<dim3(DD / 256, MR / 128), 256, GEMM_SMEM>>>(
        xh, fcwT, fc_b, cc, x, x2, nullptr, MR, DD, DD);

    // 4) x3h = half(LN(x2))
    ln2_kernel<<<MR, 256>>>(x2, ln_g, ln_b, x3h);

    // 5) h1h = half(silu(x3 @ w1 + b1))
    gemm_hmma<1><<<dim3(FFD / 256, MR / 128), 256, GEMM_SMEM>>>(
        x3h, w1T, b1, nullptr, nullptr, nullptr, h1h, MR, FFD, DD);

    // 6) out = x2 + h1 @ w2 + b2
    gemm_hmma<2><<<dim3(DD / 256, MR / 128), 256, GEMM_SMEM>>>(
        h1h, w2T, b2, x2, nullptr, out, nullptr, MR, DD, FFD);
}

// round 9
// speedup vs baseline: 1.2673x; 1.2673x over previous
#include <cuda_runtime.h>
#include <cuda_fp16.h>
#include <math.h>
#include <stdint.h>

// ---------------------------------------------------------------------------
// Problem constants
// ---------------------------------------------------------------------------
#define BB   4
#define LL   4096
#define DD   1024
#define FFD  2048
#define MR   (BB*LL)          // 16384 rows
#define CCH  32               // conv chunks
#define CLEN 128              // conv chunk length

// ---------------------------------------------------------------------------
// Scratch (static __device__ arrays — allocation-free)
// ---------------------------------------------------------------------------
__device__ __half g_xn [(size_t)MR * DD];    // LN(x) fp16 (conv input)
__device__ __half g_c  [(size_t)MR * DD];    // conv output (fp16)
__device__ float  g_x2 [(size_t)MR * DD];    // c*y + x
__device__ __half g_xh [(size_t)MR * DD];    // fp16 copy of x (GEMM0 A)
__device__ __half g_x3h[(size_t)MR * DD];    // fp16 LN(x2)    (GEMM1 A)
__device__ __half g_h1h[(size_t)MR * FFD];   // fp16 silu(x3@w1+b1) (GEMM2 A)
__device__ __half g_fcwT[(size_t)DD * DD];   // fc_w^T fp16 [N,K]
__device__ __half g_w1T [(size_t)FFD * DD];  // w1^T  fp16 [FF,D]
__device__ __half g_w2T [(size_t)DD * FFD];  // w2^T  fp16 [D,FF]
__device__ float  g_Ere[(size_t)BB * CCH * DD];
__device__ float  g_Eim[(size_t)BB * CCH * DD];

// ---------------------------------------------------------------------------
// PTX helpers (sm_100 base target — NO tcgen05)
// ---------------------------------------------------------------------------
__device__ __forceinline__ uint32_t smem_u32(const void* p) {
    uint32_t a;
    asm("{ .reg .u64 t; cvta.to.shared.u64 t, %1; cvt.u32.u64 %0, t; }"
        : "=r"(a) : "l"(p));
    return a;
}
__device__ __forceinline__ void cp16(uint32_t dst, const void* src) {
    asm volatile("cp.async.cg.shared.global [%0], [%1], 16;"
                 :: "r"(dst), "l"(src));
}
#define CP_COMMIT() asm volatile("cp.async.commit_group;" ::: "memory")
#define CP_WAIT1()  asm volatile("cp.async.wait_group 1;" ::: "memory")

__device__ __forceinline__ void ldsm4(uint32_t* r, uint32_t addr) {
    asm volatile("ldmatrix.sync.aligned.m8n8.x4.shared.b16 {%0,%1,%2,%3}, [%4];"
                 : "=r"(r[0]), "=r"(r[1]), "=r"(r[2]), "=r"(r[3]) : "r"(addr));
}
__device__ __forceinline__ void mma16816(float* c, const uint32_t* a,
                                         uint32_t b0, uint32_t b1) {
    asm volatile(
        "mma.sync.aligned.m16n8k16.row.col.f32.f16.f16.f32 "
        "{%0,%1,%2,%3},{%4,%5,%6,%7},{%8,%9},{%0,%1,%2,%3};"
        : "+f"(c[0]), "+f"(c[1]), "+f"(c[2]), "+f"(c[3])
        : "r"(a[0]), "r"(a[1]), "r"(a[2]), "r"(a[3]), "r"(b0), "r"(b1));
}

// ---------------------------------------------------------------------------
// LayerNorm kernels
// ---------------------------------------------------------------------------
__device__ __forceinline__ void ln_stats(const float4& v, int tid,
                                         float& mean, float& rstd) {
    float s = v.x + v.y + v.z + v.w;
    float q = v.x*v.x + v.y*v.y + v.z*v.z + v.w*v.w;
    #pragma unroll
    for (int o = 16; o > 0; o >>= 1) {
        s += __shfl_down_sync(0xffffffffu, s, o);
        q += __shfl_down_sync(0xffffffffu, q, o);
    }
    __shared__ float ss[8], qq[8];
    if ((tid & 31) == 0) { ss[tid >> 5] = s; qq[tid >> 5] = q; }
    __syncthreads();
    if (tid < 32) {
        float s2 = (tid < 8) ? ss[tid] : 0.f;
        float q2 = (tid < 8) ? qq[tid] : 0.f;
        #pragma unroll
        for (int o = 4; o > 0; o >>= 1) {
            s2 += __shfl_down_sync(0xffffffffu, s2, o);
            q2 += __shfl_down_sync(0xffffffffu, q2, o);
        }
        if (tid == 0) { ss[0] = s2; qq[0] = q2; }
    }
    __syncthreads();
    mean = ss[0] * (1.f / 1024.f);
    const float var = qq[0] * (1.f / 1024.f) - mean * mean;
    rstd = rsqrtf(var + 1e-5f);
}

// LN1: xn = half(LN(x)), xh = half(x raw)
__global__ void __launch_bounds__(256) ln1_kernel(
    const float* __restrict__ x, const float* __restrict__ g,
    const float* __restrict__ b, __half* __restrict__ xn, __half* __restrict__ xh)
{
    const int row = blockIdx.x, tid = threadIdx.x;
    const float4 v = ((const float4*)x)[(size_t)row * 256 + tid];
    float mean, rstd;
    ln_stats(v, tid, mean, rstd);
    const float4 gg = ((const float4*)g)[tid];
    const float4 bb = ((const float4*)b)[tid];
    __half2 n01 = __floats2half2_rn((v.x - mean) * rstd * gg.x + bb.x,
                                    (v.y - mean) * rstd * gg.y + bb.y);
    __half2 n23 = __floats2half2_rn((v.z - mean) * rstd * gg.z + bb.z,
                                    (v.w - mean) * rstd * gg.w + bb.w);
    uint2 un; un.x = *(uint32_t*)&n01; un.y = *(uint32_t*)&n23;
    ((uint2*)xn)[(size_t)row * 256 + tid] = un;
    __half2 h01 = __floats2half2_rn(v.x, v.y);
    __half2 h23 = __floats2half2_rn(v.z, v.w);
    uint2 u; u.x = *(uint32_t*)&h01; u.y = *(uint32_t*)&h23;
    ((uint2*)xh)[(size_t)row * 256 + tid] = u;
}

// LN2: x3h = half(LN(x2))
__global__ void __launch_bounds__(256) ln2_kernel(
    const float* __restrict__ x2, const float* __restrict__ g,
    const float* __restrict__ b, __half* __restrict__ x3h)
{
    const int row = blockIdx.x, tid = threadIdx.x;
    const float4 v = ((const float4*)x2)[(size_t)row * 256 + tid];
    float mean, rstd;
    ln_stats(v, tid, mean, rstd);
    const float4 gg = ((const float4*)g)[tid];
    const float4 bb = ((const float4*)b)[tid];
    __half2 h01 = __floats2half2_rn((v.x - mean) * rstd * gg.x + bb.x,
                                    (v.y - mean) * rstd * gg.y + bb.y);
    __half2 h23 = __floats2half2_rn((v.z - mean) * rstd * gg.z + bb.z,
                                    (v.w - mean) * rstd * gg.w + bb.w);
    uint2 u; u.x = *(uint32_t*)&h01; u.y = *(uint32_t*)&h23;
    ((uint2*)x3h)[(size_t)row * 256 + tid] = u;
}

// ---------------------------------------------------------------------------
// Weight transpose + fp32 -> fp16:  src [K,N] -> dst [N,K]
// ---------------------------------------------------------------------------
__global__ void transpose_cvt(const float* __restrict__ src,
                              __half* __restrict__ dst, int K, int N)
{
    __shared__ float t[32][33];
    const int n0 = blockIdx.x * 32, k0 = blockIdx.y * 32;
    const int tx = threadIdx.x, ty = threadIdx.y;
    #pragma unroll
    for (int i = 0; i < 4; i++)
        t[ty + i * 8][tx] = src[(size_t)(k0 + ty + i * 8) * N + n0 + tx];
    __syncthreads();
    #pragma unroll
    for (int i = 0; i < 4; i++)
        dst[(size_t)(n0 + ty + i * 8) * K + k0 + tx] =
            __float2half_rn(t[tx][ty + i * 8]);
}

// ---------------------------------------------------------------------------
// Spiral conv: chunked linear recurrence (2 passes; fp16 in/out, fp32 state)
// ---------------------------------------------------------------------------
__device__ __forceinline__ void conv_phz(const float* ph_re, const float* ph_im,
                                         int d, float& zr, float& zi) {
    const float pr = ph_re[d], pim = ph_im[d];
    const float a  = sqrtf(pr * pr + pim * pim);
    const float sc = expf(-a) / a;
    zr = pr * sc; zi = pim * sc;
}

__global__ void __launch_bounds__(256) conv_pass1(
    const __half* __restrict__ xn,
    const float* __restrict__ ph_re, const float* __restrict__ ph_im,
    float* __restrict__ Ere, float* __restrict__ Eim)
{
    const int idx = blockIdx.x * 256 + threadIdx.x;
    const int d = idx & 1023;
    const int rest = idx >> 10;
    const int b = rest >> 5;
    const int ck = rest & 31;
    float zr, zi; conv_phz(ph_re, ph_im, d, zr, zi);

    const __half* xp = xn + ((size_t)b * LL + (size_t)ck * CLEN) * DD + d;
    float sr = 0.f, si = 0.f;
    #pragma unroll 4
    for (int t = 0; t < CLEN; t++) {
        const float xv = __half2float(xp[(size_t)t * DD]);
        const float nsr = fmaf(zr, sr, fmaf(-zi, si, xv));
        const float nsi = fmaf(zr, si, zi * sr);
        sr = nsr; si = nsi;
    }
    Ere[idx] = sr; Eim[idx] = si;
}

__global__ void __launch_bounds__(256) conv_pass3(
    const __half* __restrict__ xn,
    const float* __restrict__ ph_re, const float* __restrict__ ph_im,
    const float* __restrict__ phi_re, const float* __restrict__ phi_im,
    const float* __restrict__ lci_re, const float* __restrict__ lci_im,
    const float* __restrict__ Ere, const float* __restrict__ Eim,
    __half* __restrict__ c)
{
    const int idx = blockIdx.x * 256 + threadIdx.x;
    const int d = idx & 1023;
    const int rest = idx >> 10;
    const int b = rest >> 5;
    const int ck = rest & 31;
    float zr, zi; conv_phz(ph_re, ph_im, d, zr, zi);
    const float fr = phi_re[d], fj = phi_im[d];
    const float lr = lci_re[d], lj = lci_im[d];

    // w = phz^128 via 7 squarings
    float wr = zr, wi = zi;
    #pragma unroll
    for (int i = 0; i < 7; i++) {
        const float nr = wr * wr - wi * wi, ni = 2.f * wr * wi;
        wr = nr; wi = ni;
    }
    // p = w^ck (uniform per block -> no divergence)
    float pr = 1.f, pi = 0.f;
    int e = ck;
    float br = wr, bi = wi;
    while (e) {
        if (e & 1) { const float nr = pr * br - pi * bi, ni = pr * bi + pi * br; pr = nr; pi = ni; }
        const float nr = br * br - bi * bi, ni = 2.f * br * bi;
        br = nr; bi = ni;
        e >>= 1;
    }
    // u = lci * phz * p  (= lci * phz^(ck*128+1))
    const float tr = lr * zr - lj * zi, ti = lr * zi + lj * zr;
    float ur = tr * pr - ti * pi, ui = tr * pi + ti * pr;

    // chunk-initial state: s = sum_{cc<ck} w^(ck-1-cc) * E[cc]
    float sr = 0.f, si = 0.f;
    for (int cc = 0; cc < ck; cc++) {
        const size_t eo = ((size_t)(b * CCH + cc) << 10) + d;
        const float er = Ere[eo], ei = Eim[eo];
        const float nsr = wr * sr - wi * si + er;
        const float nsi = wr * si + wi * sr + ei;
        sr = nsr; si = nsi;
    }

    const __half* xp = xn + ((size_t)b * LL + (size_t)ck * CLEN) * DD + d;
    __half*       cp = c  + ((size_t)b * LL + (size_t)ck * CLEN) * DD + d;

#define CSTEP(XV, OUT) {                                   \
        const float nsr = fmaf(zr, sr, fmaf(-zi, si, (XV)));\
        const float nsi = fmaf(zr, si, zi * sr);            \
        sr = nsr; si = nsi;                                 \
        (OUT) = fmaf(fr, sr, fmaf(-fj, si, ur));            \
        const float nur = zr * ur - zi * ui;                \
        const float nui = zr * ui + zi * ur;                \
        ur = nur; ui = nui; }

    for (int t = 0; t < CLEN; t += 4) {
        const float x0 = __half2float(xp[0 * DD]);
        const float x1 = __half2float(xp[1 * DD]);
        const float x2 = __half2float(xp[2 * DD]);
        const float x3 = __half2float(xp[3 * DD]);
        float c0, c1, c2, c3;
        CSTEP(x0, c0); CSTEP(x1, c1); CSTEP(x2, c2); CSTEP(x3, c3);
        cp[0 * DD] = __float2half_rn(c0);
        cp[1 * DD] = __float2half_rn(c1);
        cp[2 * DD] = __float2half_rn(c2);
        cp[3 * DD] = __float2half_rn(c3);
        xp += 4 * DD; cp += 4 * DD;
    }
#undef CSTEP
}

// ---------------------------------------------------------------------------
// fp16 mma.sync GEMM: out = epi(A[M,K] @ B^T + bias),  B stored [N,K] fp16.
//   BM=128, BN=128, BK=64, 3-stage cp.async pipeline, ldmatrix, m16n8k16.
//   8 warps: wm = wid&1 (64 rows), wn = wid>>1 (32 cols). Warp tile 64x32.
//   110592B smem x 2 CTAs/SM; __launch_bounds__(256,2).  [R7 config]
//   MODE 0: out = silu(v)*Ph + Q   (Ph fp16 gate, Q fp32 residual -> fp32)
//   MODE 1: out = silu(v)          (fp16)
//   MODE 2: out = v + P            (fp32)
// ---------------------------------------------------------------------------
#define ROW_B    144                     // bytes per smem row (64 h + pad)
#define SLOT_A   (128 * ROW_B)           // 18432
#define SLOT_BYTES (2 * SLOT_A)          // 36864
#define NSTAGE   3
#define GEMM_SMEM  (NSTAGE * SLOT_BYTES) // 110592

__device__ __forceinline__ void load_stage(uint32_t sslot,
                                           const __half* __restrict__ A,
                                           const __half* __restrict__ Bm,
                                           int bm, int bn, int K, int kt, int tid)
{
    const __half* ag = A + (size_t)bm * K + kt * 64;
    #pragma unroll
    for (int i = 0; i < 4; i++) {
        const int o = tid + 256 * i;           // 0..1023
        const int row = o >> 3, ch = o & 7;
        cp16(sslot + row * ROW_B + ch * 16, ag + (size_t)row * K + ch * 8);
    }
    const __half* bg = Bm + (size_t)bn * K + kt * 64;
    #pragma unroll
    for (int i = 0; i < 4; i++) {
        const int o = tid + 256 * i;
        const int row = o >> 3, ch = o & 7;
        cp16(sslot + SLOT_A + row * ROW_B + ch * 16, bg + (size_t)row * K + ch * 8);
    }
}

template <int MODE>
__global__ void __launch_bounds__(256, 2)
gemm_hmma(const __half* __restrict__ A, const __half* __restrict__ Bm,
          const float* __restrict__ bias, const __half* __restrict__ Ph,
          const float* __restrict__ P, const float* __restrict__ Q,
          float* __restrict__ outF, __half* __restrict__ outH,
          int M, int N, int K)
{
    extern __shared__ char smem_raw[];
    const uint32_t sbase = smem_u32(smem_raw);

    const int tid = threadIdx.x, wid = tid >> 5, lane = tid & 31;
    const int wm = wid & 1, wn = wid >> 1;
    const int bm = blockIdx.y << 7, bn = blockIdx.x << 7;
    const int KT = K >> 6;

    // lane-dependent ldmatrix address part: row = lane&15, khalf = lane>>4
    const uint32_t lane_off = (uint32_t)(lane & 15) * ROW_B + (uint32_t)(lane >> 4) * 16;

    float acc[4][4][4];
    #pragma unroll
    for (int i = 0; i < 4; i++)
        #pragma unroll
        for (int j = 0; j < 4; j++)
            #pragma unroll
            for (int k = 0; k < 4; k++) acc[i][j][k] = 0.f;

    // prologue: stages 0..1
    #pragma unroll
    for (int s = 0; s < 2; s++) {
        load_stage(sbase + s * SLOT_BYTES, A, Bm, bm, bn, K, s, tid);
        CP_COMMIT();
    }

    int slot = 0, wslot = 2;
    for (int kt = 0; kt < KT; kt++) {
        CP_WAIT1();
        __syncthreads();

        const uint32_t sA = sbase + slot * SLOT_BYTES;
        const uint32_t sB = sA + SLOT_A;
        const uint32_t aw = sA + (uint32_t)(wm * 64) * ROW_B + lane_off;
        const uint32_t bw = sB + (uint32_t)(wn * 32) * ROW_B + lane_off;

        #pragma unroll
        for (int ks = 0; ks < 4; ks++) {
            uint32_t af[4][4], bf[2][4];
            #pragma unroll
            for (int mi = 0; mi < 4; mi++)
                ldsm4(af[mi], aw + (uint32_t)(mi * 16) * ROW_B + ks * 32);
            #pragma unroll
            for (int nj = 0; nj < 2; nj++)
                ldsm4(bf[nj], bw + (uint32_t)(nj * 16) * ROW_B + ks * 32);
            #pragma unroll
            for (int mi = 0; mi < 4; mi++)
                #pragma unroll
                for (int ni = 0; ni < 4; ni++) {
                    const int nj = ni >> 1, hi = ni & 1;
                    mma16816(acc[mi][ni], af[mi], bf[nj][hi], bf[nj][2 + hi]);
                }
        }

        const int kn = kt + 2;
        if (kn < KT)
            load_stage(sbase + wslot * SLOT_BYTES, A, Bm, bm, bn, K, kn, tid);
        CP_COMMIT();

        slot = (slot + 1 == NSTAGE) ? 0 : slot + 1;
        wslot = (wslot + 1 == NSTAGE) ? 0 : wslot + 1;
    }

    // ---------------- epilogue ----------------
    #pragma unroll
    for (int mi = 0; mi < 4; ++mi) {
        #pragma unroll
        for (int ni = 0; ni < 4; ++ni) {
            const int r0 = bm + wm * 64 + mi * 16 + (lane >> 2);
            const int c0 = bn + wn * 32 + ni * 8 + (lane & 3) * 2;
            const float2 bz = *(const float2*)(bias + c0);

            #pragma unroll
            for (int half = 0; half < 2; ++half) {
                const int r = r0 + half * 8;
                float v0 = acc[mi][ni][half * 2 + 0] + bz.x;
                float v1 = acc[mi][ni][half * 2 + 1] + bz.y;
                const size_t off = (size_t)r * N + c0;
                if (MODE == 0 || MODE == 1) {
                    v0 = v0 / (1.f + expf(-v0));
                    v1 = v1 / (1.f + expf(-v1));
                }
                if (MODE == 0) {
                    const uint32_t pu = *(const uint32_t*)(Ph + off);
                    const __half2 ph2 = *(const __half2*)&pu;
                    const float2 pf = __half22float2(ph2);
                    const float2 q = *(const float2*)(Q + off);
                    v0 = fmaf(v0, pf.x, q.x);
                    v1 = fmaf(v1, pf.y, q.y);
                }
                if (MODE == 2) {
                    const float2 p = *(const float2*)(P + off);
                    v0 += p.x;
                    v1 += p.y;
                }
                if (MODE == 1) {
                    __half2 h = __floats2half2_rn(v0, v1);
                    *(uint32_t*)(outH + off) = *(uint32_t*)&h;
                } else {
                    *(float2*)(outF + off) = make_float2(v0, v1);
                }
            }
        }
    }
}

// ---------------------------------------------------------------------------
// kernel_launch
// Inputs: 0 x, 1 ln_g, 2 ln_b, 3 fc_w, 4 fc_b, 5 w1, 6 b1, 7 w2, 8 b2,
//         9 ph_re, 10 ph_im, 11 phi_re, 12 phi_im, 13 lci_re, 14 lci_im
// ---------------------------------------------------------------------------
extern "C" void kernel_launch(void* const* d_in, const int* in_sizes, int n_in,
                              void* d_out, int out_size)
{
    const float* x      = (const float*)d_in[0];
    const float* ln_g   = (const float*)d_in[1];
    const float* ln_b   = (const float*)d_in[2];
    const float* fc_w   = (const float*)d_in[3];
    const float* fc_b   = (const float*)d_in[4];
    const float* w1     = (const float*)d_in[5];
    const float* b1     = (const float*)d_in[6];
    const float* w2     = (const float*)d_in[7];
    const float* b2     = (const float*)d_in[8];
    const float* ph_re  = (const float*)d_in[9];
    const float* ph_im  = (const float*)d_in[10];
    const float* phi_re = (const float*)d_in[11];
    const float* phi_im = (const float*)d_in[12];
    const float* lci_re = (const float*)d_in[13];
    const float* lci_im = (const float*)d_in[14];
    float* out = (float*)d_out;

    void *p;
    cudaGetSymbolAddress(&p, g_xn);   __half* xn   = (__half*)p;
    cudaGetSymbolAddress(&p, g_c);    __half* cc   = (__half*)p;
    cudaGetSymbolAddress(&p, g_x2);   float*  x2   = (float*)p;
    cudaGetSymbolAddress(&p, g_xh);   __half* xh   = (__half*)p;
    cudaGetSymbolAddress(&p, g_x3h);  __half* x3h  = (__half*)p;
    cudaGetSymbolAddress(&p, g_h1h);  __half* h1h  = (__half*)p;
    cudaGetSymbolAddress(&p, g_fcwT); __half* fcwT = (__half*)p;
    cudaGetSymbolAddress(&p, g_w1T);  __half* w1T  = (__half*)p;
    cudaGetSymbolAddress(&p, g_w2T);  __half* w2T  = (__half*)p;
    cudaGetSymbolAddress(&p, g_Ere);  float*  Ere  = (float*)p;
    cudaGetSymbolAddress(&p, g_Eim);  float*  Eim  = (float*)p;

    cudaFuncSetAttribute(gemm_hmma<0>, cudaFuncAttributeMaxDynamicSharedMemorySize, GEMM_SMEM);
    cudaFuncSetAttribute(gemm_hmma<1>, cudaFuncAttributeMaxDynamicSharedMemorySize, GEMM_SMEM);
    cudaFuncSetAttribute(gemm_hmma<2>, cudaFuncAttributeMaxDynamicSharedMemorySize, GEMM_SMEM);

    // weight transpose + fp16 convert
    transpose_cvt<<<dim3(DD / 32, DD / 32),  dim3(32, 8)>>>(fc_w, fcwT, DD, DD);
    transpose_cvt<<<dim3(FFD / 32, DD / 32), dim3(32, 8)>>>(w1,   w1T,  DD, FFD);
    transpose_cvt<<<dim3(DD / 32, FFD / 32), dim3(32, 8)>>>(w2,   w2T,  FFD, DD);

    // 1) xn = half(LN(x)), xh = half(x)
    ln1_kernel<<<MR, 256>>>(x, ln_g, ln_b, xn, xh);

    // 2) c = spiral_conv(xn) — 2-pass chunked scan (fp16 I/O, fp32 state)
    conv_pass1<<<(BB * CCH * DD) / 256, 256>>>(xn, ph_re, ph_im, Ere, Eim);
    conv_pass3<<<(BB * CCH * DD) / 256, 256>>>(xn, ph_re, ph_im, phi_re, phi_im,
                                               lci_re, lci_im, Ere, Eim, cc);

    // 3) x2 = silu(x@fc_w + fc_b) * c + x
    gemm_hmma<0><<<dim3(DD / 128, MR / 128), 256, GEMM_SMEM>>>(
        xh, fcwT, fc_b, cc, nullptr, x, x2, nullptr, MR, DD, DD);

    // 4) x3h = half(LN(x2))
    ln2_kernel<<<MR, 256>>>(x2, ln_g, ln_b, x3h);

    // 5) h1h = half(silu(x3 @ w1 + b1))
    gemm_hmma<1><<<dim3(FFD / 128, MR / 128), 256, GEMM_SMEM>>>(
        x3h, w1T, b1, nullptr, nullptr, nullptr, nullptr, h1h, MR, FFD, DD);

    // 6) out = x2 + h1 @ w2 + b2
    gemm_hmma<2><<<dim3(DD / 128, MR / 128), 256, GEMM_SMEM>>>(
        h1h, w2T, b2, nullptr, x2, nullptr, out, nullptr, MR, DD, FFD);
}